// round 6
// baseline (speedup 1.0000x reference)
#include <cuda_runtime.h>

#define BB 8
#define HH 256
#define WW 256
#define NPIX (BB*HH*WW)

// ---------------- device scratch ----------------
__device__ float g_y1[BB*32*HH*WW];
__device__ float g_y2[(size_t)BB*64*HH*WW];
__device__ float g_stats[2*(32+64+128)];
__device__ float g_aff[2*(32+64+128)];
__device__ float g_gath[BB*128];

__global__ void zero_stats() {
    int i = blockIdx.x*blockDim.x + threadIdx.x;
    if (i < 448) g_stats[i] = 0.f;
}

// packed f32x2 helpers
__device__ __forceinline__ unsigned long long pack2(float lo, float hi) {
    unsigned long long r;
    asm("mov.b64 %0, {%1, %2};" : "=l"(r) : "f"(lo), "f"(hi));
    return r;
}
__device__ __forceinline__ void unpack2(unsigned long long v, float& lo, float& hi) {
    asm("mov.b64 {%0, %1}, %2;" : "=f"(lo), "=f"(hi) : "l"(v));
}
__device__ __forceinline__ void fma2(unsigned long long& d,
                                     unsigned long long a, unsigned long long b) {
    asm("fma.rn.f32x2 %0, %1, %2, %0;" : "+l"(d) : "l"(a), "l"(b));
}

// ---------------- fused conv3x3, pixel-packed f32x2 ----------------
// 256 threads. Output tile 32(W) x 16(H) x 16 couts.
// Thread (tx,ty,tz): 8 adjacent cols [8tx,8tx+8) in row ty, 4 couts [4tz,4tz+4).
// tz = tid>>6 -> warp-uniform (weight loads are pure broadcasts).
// Accumulators: 4 couts x 4 pixel-pairs of f32x2.
template<int CIN, int COUT, bool APPLY_IN, bool WRITE_OUT, bool GATHER, bool DUPW>
__global__ __launch_bounds__(256, 2)
void conv3x3(const float* __restrict__ in,
             const float* __restrict__ w,      // [COUT,CIN,3,3]
             const float* __restrict__ bias,
             const float* __restrict__ aff,    // input affine: scale[CIN], shift[CIN]
             float* __restrict__ out,
             float* __restrict__ stats,
             float* __restrict__ gath,
             const int* __restrict__ nxy)
{
    __shared__ __align__(16) float s_w[DUPW ? CIN*9*16*2 : CIN*9*16];
    __shared__ __align__(16) float s_in[2][18][35];   // stride 35: conflict-free scalar loads
    __shared__ float s_red[2][16][2];

    const int tid = threadIdx.x;
    const int tx = tid & 3;
    const int ty = (tid >> 2) & 15;
    const int tz = tid >> 6;                 // warp-uniform
    const int tileX = blockIdx.x * 32, tileY = blockIdx.y * 16;
    const int ng  = COUT / 16;
    const int cog = blockIdx.z % ng;
    const int b   = blockIdx.z / ng;
    const int co0 = cog * 16;

    // ---- preload weights transposed to [ci][k][o] (duplicated (w,w) if DUPW)
    for (int e = tid; e < CIN*144; e += 256) {
        int ci  = e / 144;
        int rem = e - ci*144;
        int o   = rem / 9;
        int k   = rem - o*9;
        float wv = w[((co0 + o)*CIN + ci)*9 + k];
        if (DUPW) {
            *reinterpret_cast<float2*>(&s_w[((ci*9 + k)*16 + o)*2]) = make_float2(wv, wv);
        } else {
            s_w[(ci*9 + k)*16 + o] = wv;
        }
    }

    auto load_tile = [&](int ci, int buf) {
        const float* inp = in + ((size_t)(b*CIN + ci))*HH*WW;
        const float sA = APPLY_IN ? aff[ci]       : 0.f;
        const float sB = APPLY_IN ? aff[CIN + ci] : 0.f;
        #pragma unroll
        for (int e = tid; e < 18*34; e += 256) {
            int r = e / 34, c = e - r*34;
            int gy = tileY + r - 1, gx = tileX + c - 1;
            float v = 0.f;
            if ((unsigned)gy < (unsigned)HH && (unsigned)gx < (unsigned)WW) {
                v = inp[gy*WW + gx];
                if (APPLY_IN) {
                    v = fmaf(sA, v, sB);
                    v = (v > 0.f) ? v : 0.01f*v;
                }
            }
            s_in[buf][r][c] = v;
        }
    };

    // accP[o][p]: cout o, pixel pair p (cols 8tx+2p, 8tx+2p+1)
    unsigned long long accP[4][4];
    #pragma unroll
    for (int o = 0; o < 4; ++o)
        #pragma unroll
        for (int p = 0; p < 4; ++p) accP[o][p] = 0ull;

    load_tile(0, 0);
    __syncthreads();

    for (int ci = 0; ci < CIN; ++ci) {
        const int buf = ci & 1;
        if (ci + 1 < CIN) load_tile(ci + 1, buf ^ 1);

        #pragma unroll
        for (int r = 0; r < 3; ++r) {
            // 10 scalar window loads (conflict-free: 3*(ty+r)+8tx+i distinct mod 32)
            float v[10];
            #pragma unroll
            for (int i = 0; i < 10; ++i) v[i] = s_in[buf][ty + r][8*tx + i];

            // 9 unique pairs: E0..E4 even, O0..O3 odd
            unsigned long long E[5], O[4];
            #pragma unroll
            for (int p = 0; p < 5; ++p) E[p] = pack2(v[2*p], v[2*p + 1]);
            #pragma unroll
            for (int p = 0; p < 4; ++p) O[p] = pack2(v[2*p + 1], v[2*p + 2]);

            #pragma unroll
            for (int c = 0; c < 3; ++c) {
                const int k = 3*r + c;
                unsigned long long wp2[4];
                if (DUPW) {
                    // 2 x LDS.128, uniform address (broadcast, N=1)
                    const float* wq = &s_w[((ci*9 + k)*16 + 4*tz)*2];
                    asm("ld.shared.v2.b64 {%0, %1}, [%2];"
                        : "=l"(wp2[0]), "=l"(wp2[1])
                        : "r"((unsigned)__cvta_generic_to_shared(wq)));
                    asm("ld.shared.v2.b64 {%0, %1}, [%2];"
                        : "=l"(wp2[2]), "=l"(wp2[3])
                        : "r"((unsigned)__cvta_generic_to_shared(wq + 4)));
                } else {
                    const float* wq = &s_w[(ci*9 + k)*16 + 4*tz];
                    #pragma unroll
                    for (int o = 0; o < 4; ++o) { float wv = wq[o]; wp2[o] = pack2(wv, wv); }
                }
                // select pair set for this tap alignment
                unsigned long long pr[4];
                if (c == 0)      { pr[0]=E[0]; pr[1]=E[1]; pr[2]=E[2]; pr[3]=E[3]; }
                else if (c == 1) { pr[0]=O[0]; pr[1]=O[1]; pr[2]=O[2]; pr[3]=O[3]; }
                else             { pr[0]=E[1]; pr[1]=E[2]; pr[2]=E[3]; pr[3]=E[4]; }

                #pragma unroll
                for (int o = 0; o < 4; ++o)
                    #pragma unroll
                    for (int p = 0; p < 4; ++p)
                        fma2(accP[o][p], wp2[o], pr[p]);
            }
        }
        __syncthreads();
    }

    // ---- unpack + bias
    float a[4][8];
    #pragma unroll
    for (int o = 0; o < 4; ++o) {
        float bv = bias[co0 + 4*tz + o];
        #pragma unroll
        for (int p = 0; p < 4; ++p) {
            float lo, hi; unpack2(accP[o][p], lo, hi);
            a[o][2*p] = lo + bv; a[o][2*p + 1] = hi + bv;
        }
    }

    const int y   = tileY + ty;
    const int x0b = tileX + 8*tx;

    if (WRITE_OUT) {
        #pragma unroll
        for (int o = 0; o < 4; ++o) {
            float* dst = &out[(((size_t)b*COUT + co0 + 4*tz + o)*HH + y)*WW + x0b];
            *reinterpret_cast<float4*>(dst)     = make_float4(a[o][0], a[o][1], a[o][2], a[o][3]);
            *reinterpret_cast<float4*>(dst + 4) = make_float4(a[o][4], a[o][5], a[o][6], a[o][7]);
        }
    }

    if (GATHER) {
        const int ny = nxy[b*64 + 62];
        const int nx = nxy[b*64 + 63];
        if (y == ny && nx >= x0b && nx < x0b + 8) {
            #pragma unroll
            for (int o = 0; o < 4; ++o)
                gath[b*COUT + co0 + 4*tz + o] = a[o][nx - x0b];
        }
    }

    // ---- BN stats: warp reduce (tz uniform per warp), 2 warps per cout-group
    const int lane = tid & 31;
    const int wslot = (tid >> 5) & 1;
    #pragma unroll
    for (int o = 0; o < 4; ++o) {
        float s = 0.f, ss = 0.f;
        #pragma unroll
        for (int j = 0; j < 8; ++j) { s += a[o][j]; ss += a[o][j]*a[o][j]; }
        #pragma unroll
        for (int off = 16; off; off >>= 1) {
            s  += __shfl_down_sync(0xffffffffu, s,  off);
            ss += __shfl_down_sync(0xffffffffu, ss, off);
        }
        if (lane == 0) { s_red[0][4*tz + o][wslot] = s; s_red[1][4*tz + o][wslot] = ss; }
    }
    __syncthreads();
    if (tid < 16) {
        atomicAdd(&stats[co0 + tid],        s_red[0][tid][0] + s_red[0][tid][1]);
        atomicAdd(&stats[COUT + co0 + tid], s_red[1][tid][0] + s_red[1][tid][1]);
    }
}

// ---------------- BN finalize ----------------
__global__ void finalize_aff(int C, int off,
                             const float* __restrict__ gamma,
                             const float* __restrict__ beta)
{
    int c = threadIdx.x;
    if (c < C) {
        const float n = (float)NPIX;
        float m = g_stats[off + c] / n;
        float v = g_stats[off + C + c] / n - m*m;
        float a = gamma[c] * rsqrtf(v + 1e-5f);
        g_aff[off + c]     = a;
        g_aff[off + C + c] = beta[c] - m*a;
    }
}

// ---------------- tail ----------------
__global__ void tail_kernel(const float* __restrict__ image,
                            const int* __restrict__ axy,
                            const int* __restrict__ pxy,
                            const int* __restrict__ nxy,
                            float* __restrict__ out)
{
    int i = blockIdx.x*blockDim.x + threadIdx.x;
    if (i < 3528) {
        int which = i / 1176;
        int rem   = i % 1176;
        int b  = rem / 147;
        int r2 = rem % 147;
        int c  = r2 / 49;
        int p  = r2 % 49;
        int pi = p / 7, pj = p % 7;
        const int* xy = (which == 0) ? axy : (which == 1) ? pxy : nxy;
        int y0 = xy[b*64 + 62] - 3;
        int x0 = xy[b*64 + 63] - 3;
        out[i] = image[((b*3 + c)*HH + (y0 + pi))*WW + (x0 + pj)];
    } else if (i < 3528 + 1024) {
        int j = i - 3528;
        int c = j & 127;
        float v = fmaf(g_aff[192 + c], g_gath[j], g_aff[192 + 128 + c]);
        out[i] = (v > 0.f) ? v : 0.01f*v;
    }
}

// ---------------- launch ----------------
extern "C" void kernel_launch(void* const* d_in, const int* in_sizes, int n_in,
                              void* d_out, int out_size)
{
    const float* image = (const float*)d_in[0];
    const int*   axy   = (const int*)  d_in[1];
    const int*   pxy   = (const int*)  d_in[2];
    const int*   nxy   = (const int*)  d_in[3];
    const float* w1 = (const float*)d_in[4];
    const float* b1 = (const float*)d_in[5];
    const float* g1 = (const float*)d_in[6];
    const float* e1 = (const float*)d_in[7];
    const float* w2 = (const float*)d_in[8];
    const float* b2 = (const float*)d_in[9];
    const float* g2 = (const float*)d_in[10];
    const float* e2 = (const float*)d_in[11];
    const float* w3 = (const float*)d_in[12];
    const float* b3 = (const float*)d_in[13];
    const float* g3 = (const float*)d_in[14];
    const float* e3 = (const float*)d_in[15];
    float* outp = (float*)d_out;

    float *y1, *y2, *stats, *aff, *gath;
    cudaGetSymbolAddress((void**)&y1,    g_y1);
    cudaGetSymbolAddress((void**)&y2,    g_y2);
    cudaGetSymbolAddress((void**)&stats, g_stats);
    cudaGetSymbolAddress((void**)&aff,   g_aff);
    cudaGetSymbolAddress((void**)&gath,  g_gath);

    dim3 blk(256);

    zero_stats<<<2, 256>>>();

    // conv1: CIN=3, dup'd weights (tiny smem)
    conv3x3<3, 32, false, true, false, true><<<dim3(8,16,BB*2), blk>>>(
        image, w1, b1, nullptr, y1, stats + 0, nullptr, nullptr);
    finalize_aff<<<1, 32>>>(32, 0, g1, e1);

    // conv2: CIN=32, dup'd weights (36 KB smem)
    conv3x3<32, 64, true, true, false, true><<<dim3(8,16,BB*4), blk>>>(
        y1, w2, b2, aff + 0, y2, stats + 64, nullptr, nullptr);
    finalize_aff<<<1, 64>>>(64, 64, g2, e2);

    // conv3: CIN=64, scalar weights (stays under 48 KB static smem)
    conv3x3<64, 128, true, false, true, false><<<dim3(8,16,BB*8), blk>>>(
        y2, w3, b3, aff + 64, nullptr, stats + 192, gath, nxy);
    finalize_aff<<<1, 128>>>(128, 192, g3, e3);

    tail_kernel<<<(3528 + 1024 + 255)/256, 256>>>(image, axy, pxy, nxy, outp);
}

// round 7
// speedup vs baseline: 1.3118x; 1.3118x over previous
#include <cuda_runtime.h>

#define BB 8
#define HH 256
#define WW 256
#define NPIX (BB*HH*WW)

// ---------------- device scratch ----------------
__device__ float g_y1[BB*32*HH*WW];
__device__ float g_y2[(size_t)BB*64*HH*WW];
__device__ float g_stats[2*(32+64+128)];
__device__ float g_aff[2*(32+64+128)];
__device__ float g_gath[BB*128];

__global__ void zero_stats() {
    int i = blockIdx.x*blockDim.x + threadIdx.x;
    if (i < 448) g_stats[i] = 0.f;
}

// packed f32x2 helpers
__device__ __forceinline__ unsigned long long pack2(float lo, float hi) {
    unsigned long long r;
    asm("mov.b64 %0, {%1, %2};" : "=l"(r) : "f"(lo), "f"(hi));
    return r;
}
__device__ __forceinline__ void unpack2(unsigned long long v, float& lo, float& hi) {
    asm("mov.b64 {%0, %1}, %2;" : "=f"(lo), "=f"(hi) : "l"(v));
}
__device__ __forceinline__ void fma2(unsigned long long& d,
                                     unsigned long long a, unsigned long long b) {
    asm("fma.rn.f32x2 %0, %1, %2, %0;" : "+l"(d) : "l"(a), "l"(b));
}

// ---------------- fused conv3x3 (cout-pair f32x2, 4 px/thread) ----------------
// 256 threads. Output tile 64(W) x 16(H) x 16 couts.
// Thread (tx,ty): 4 adjacent cols [4tx,4tx+4) in row ty, all 16 couts.
// Accumulators: 8 cout-pairs x 4 pixels (f32x2 packed over cout-pairs so
// weights load as natural LDS.128 from smem — no duplication, no weight movs).
template<int CIN, int COUT, bool APPLY_IN, bool WRITE_OUT, bool GATHER>
__global__ __launch_bounds__(256, 2)
void conv3x3(const float* __restrict__ in,
             const float* __restrict__ w,      // [COUT,CIN,3,3]
             const float* __restrict__ bias,
             const float* __restrict__ aff,    // input affine: scale[CIN], shift[CIN]
             float* __restrict__ out,
             float* __restrict__ stats,
             float* __restrict__ gath,
             const int* __restrict__ nxy)
{
    __shared__ __align__(16) float s_w[CIN*9*16];     // [ci][k][o]
    __shared__ __align__(16) float s_in[2][18][66];   // 64+2 halo, double buffered
    __shared__ float s_red[2][16][8];

    const int tid = threadIdx.x;
    const int tx = tid & 15;          // 16 groups of 4 cols
    const int ty = tid >> 4;          // 16 rows
    const int tileX = blockIdx.x * 64, tileY = blockIdx.y * 16;
    const int ng  = COUT / 16;
    const int cog = blockIdx.z % ng;
    const int b   = blockIdx.z / ng;
    const int co0 = cog * 16;

    // ---- preload all weights transposed to [ci][k][o]
    for (int e = tid; e < CIN*144; e += 256) {
        int ci  = e / 144;
        int rem = e - ci*144;
        int o   = rem / 9;
        int k   = rem - o*9;
        s_w[(ci*9 + k)*16 + o] = w[((co0 + o)*CIN + ci)*9 + k];
    }

    auto load_tile = [&](int ci, int buf) {
        const float* inp = in + ((size_t)(b*CIN + ci))*HH*WW;
        const float sA = APPLY_IN ? aff[ci]       : 0.f;
        const float sB = APPLY_IN ? aff[CIN + ci] : 0.f;
        #pragma unroll
        for (int e = tid; e < 18*66; e += 256) {
            int r = e / 66, c = e - r*66;
            int gy = tileY + r - 1, gx = tileX + c - 1;
            float v = 0.f;
            if ((unsigned)gy < (unsigned)HH && (unsigned)gx < (unsigned)WW) {
                v = inp[gy*WW + gx];
                if (APPLY_IN) {
                    v = fmaf(sA, v, sB);
                    v = (v > 0.f) ? v : 0.01f*v;
                }
            }
            s_in[buf][r][c] = v;
        }
    };

    // acc[pr][px]: cout pair pr (couts 2pr,2pr+1), pixel px (col 4tx+px)
    unsigned long long acc[8][4];
    #pragma unroll
    for (int pr = 0; pr < 8; ++pr)
        #pragma unroll
        for (int px = 0; px < 4; ++px) acc[pr][px] = 0ull;

    load_tile(0, 0);
    __syncthreads();

    for (int ci = 0; ci < CIN; ++ci) {
        const int buf = ci & 1;
        if (ci + 1 < CIN) load_tile(ci + 1, buf ^ 1);

        #pragma unroll
        for (int r = 0; r < 3; ++r) {
            // window: 6 cols starting at 4tx (even -> 8B-aligned LDS.64 x3)
            float2 xa = *reinterpret_cast<const float2*>(&s_in[buf][ty + r][4*tx]);
            float2 xb = *reinterpret_cast<const float2*>(&s_in[buf][ty + r][4*tx + 2]);
            float2 xc = *reinterpret_cast<const float2*>(&s_in[buf][ty + r][4*tx + 4]);
            unsigned long long X[6];
            X[0] = pack2(xa.x, xa.x); X[1] = pack2(xa.y, xa.y);
            X[2] = pack2(xb.x, xb.x); X[3] = pack2(xb.y, xb.y);
            X[4] = pack2(xc.x, xc.x); X[5] = pack2(xc.y, xc.y);

            #pragma unroll
            for (int c = 0; c < 3; ++c) {
                const int k = 3*r + c;
                const float* wq = &s_w[(ci*9 + k)*16];
                unsigned long long W8[8];
                asm("ld.shared.v2.b64 {%0, %1}, [%2];"
                    : "=l"(W8[0]), "=l"(W8[1])
                    : "r"((unsigned)__cvta_generic_to_shared(wq)));
                asm("ld.shared.v2.b64 {%0, %1}, [%2];"
                    : "=l"(W8[2]), "=l"(W8[3])
                    : "r"((unsigned)__cvta_generic_to_shared(wq + 4)));
                asm("ld.shared.v2.b64 {%0, %1}, [%2];"
                    : "=l"(W8[4]), "=l"(W8[5])
                    : "r"((unsigned)__cvta_generic_to_shared(wq + 8)));
                asm("ld.shared.v2.b64 {%0, %1}, [%2];"
                    : "=l"(W8[6]), "=l"(W8[7])
                    : "r"((unsigned)__cvta_generic_to_shared(wq + 12)));

                #pragma unroll
                for (int pr = 0; pr < 8; ++pr)
                    #pragma unroll
                    for (int px = 0; px < 4; ++px)
                        fma2(acc[pr][px], W8[pr], X[c + px]);
            }
        }
        __syncthreads();
    }

    // ---- unpack + bias
    float a[16][4];
    #pragma unroll
    for (int pr = 0; pr < 8; ++pr)
        #pragma unroll
        for (int px = 0; px < 4; ++px)
            unpack2(acc[pr][px], a[2*pr][px], a[2*pr + 1][px]);
    #pragma unroll
    for (int o = 0; o < 16; ++o) {
        float bv = bias[co0 + o];
        #pragma unroll
        for (int px = 0; px < 4; ++px) a[o][px] += bv;
    }

    const int y   = tileY + ty;
    const int x0b = tileX + 4*tx;

    if (WRITE_OUT) {
        #pragma unroll
        for (int o = 0; o < 16; ++o) {
            *reinterpret_cast<float4*>(
                &out[(((size_t)b*COUT + co0 + o)*HH + y)*WW + x0b]) =
                make_float4(a[o][0], a[o][1], a[o][2], a[o][3]);
        }
    }

    if (GATHER) {
        const int ny = nxy[b*64 + 62];
        const int nx = nxy[b*64 + 63];
        if (y == ny && nx >= x0b && nx < x0b + 4) {
            #pragma unroll
            for (int o = 0; o < 16; ++o)
                gath[b*COUT + co0 + o] = a[o][nx - x0b];
        }
    }

    // ---- BN stats: warp shuffle then one atomicAdd per channel
    const int lane = tid & 31, wid = tid >> 5;
    #pragma unroll
    for (int o = 0; o < 16; ++o) {
        float s = 0.f, ss = 0.f;
        #pragma unroll
        for (int px = 0; px < 4; ++px) { s += a[o][px]; ss += a[o][px]*a[o][px]; }
        #pragma unroll
        for (int off = 16; off; off >>= 1) {
            s  += __shfl_down_sync(0xffffffffu, s,  off);
            ss += __shfl_down_sync(0xffffffffu, ss, off);
        }
        if (lane == 0) { s_red[0][o][wid] = s; s_red[1][o][wid] = ss; }
    }
    __syncthreads();
    if (tid < 16) {
        float s = 0.f, ss = 0.f;
        #pragma unroll
        for (int k = 0; k < 8; ++k) { s += s_red[0][tid][k]; ss += s_red[1][tid][k]; }
        atomicAdd(&stats[co0 + tid],        s);
        atomicAdd(&stats[COUT + co0 + tid], ss);
    }
}

// ---------------- BN finalize ----------------
__global__ void finalize_aff(int C, int off,
                             const float* __restrict__ gamma,
                             const float* __restrict__ beta)
{
    int c = threadIdx.x;
    if (c < C) {
        const float n = (float)NPIX;
        float m = g_stats[off + c] / n;
        float v = g_stats[off + C + c] / n - m*m;
        float a = gamma[c] * rsqrtf(v + 1e-5f);
        g_aff[off + c]     = a;
        g_aff[off + C + c] = beta[c] - m*a;
    }
}

// ---------------- tail ----------------
__global__ void tail_kernel(const float* __restrict__ image,
                            const int* __restrict__ axy,
                            const int* __restrict__ pxy,
                            const int* __restrict__ nxy,
                            float* __restrict__ out)
{
    int i = blockIdx.x*blockDim.x + threadIdx.x;
    if (i < 3528) {
        int which = i / 1176;
        int rem   = i % 1176;
        int b  = rem / 147;
        int r2 = rem % 147;
        int c  = r2 / 49;
        int p  = r2 % 49;
        int pi = p / 7, pj = p % 7;
        const int* xy = (which == 0) ? axy : (which == 1) ? pxy : nxy;
        int y0 = xy[b*64 + 62] - 3;
        int x0 = xy[b*64 + 63] - 3;
        out[i] = image[((b*3 + c)*HH + (y0 + pi))*WW + (x0 + pj)];
    } else if (i < 3528 + 1024) {
        int j = i - 3528;
        int c = j & 127;
        float v = fmaf(g_aff[192 + c], g_gath[j], g_aff[192 + 128 + c]);
        out[i] = (v > 0.f) ? v : 0.01f*v;
    }
}

// ---------------- launch ----------------
extern "C" void kernel_launch(void* const* d_in, const int* in_sizes, int n_in,
                              void* d_out, int out_size)
{
    const float* image = (const float*)d_in[0];
    const int*   axy   = (const int*)  d_in[1];
    const int*   pxy   = (const int*)  d_in[2];
    const int*   nxy   = (const int*)  d_in[3];
    const float* w1 = (const float*)d_in[4];
    const float* b1 = (const float*)d_in[5];
    const float* g1 = (const float*)d_in[6];
    const float* e1 = (const float*)d_in[7];
    const float* w2 = (const float*)d_in[8];
    const float* b2 = (const float*)d_in[9];
    const float* g2 = (const float*)d_in[10];
    const float* e2 = (const float*)d_in[11];
    const float* w3 = (const float*)d_in[12];
    const float* b3 = (const float*)d_in[13];
    const float* g3 = (const float*)d_in[14];
    const float* e3 = (const float*)d_in[15];
    float* outp = (float*)d_out;

    float *y1, *y2, *stats, *aff, *gath;
    cudaGetSymbolAddress((void**)&y1,    g_y1);
    cudaGetSymbolAddress((void**)&y2,    g_y2);
    cudaGetSymbolAddress((void**)&stats, g_stats);
    cudaGetSymbolAddress((void**)&aff,   g_aff);
    cudaGetSymbolAddress((void**)&gath,  g_gath);

    dim3 blk(256);

    zero_stats<<<2, 256>>>();

    // grids: 4 x-tiles (64 wide), 16 y-tiles, z = B * (COUT/16)
    conv3x3<3, 32, false, true, false><<<dim3(4,16,BB*2), blk>>>(
        image, w1, b1, nullptr, y1, stats + 0, nullptr, nullptr);
    finalize_aff<<<1, 32>>>(32, 0, g1, e1);

    conv3x3<32, 64, true, true, false><<<dim3(4,16,BB*4), blk>>>(
        y1, w2, b2, aff + 0, y2, stats + 64, nullptr, nullptr);
    finalize_aff<<<1, 64>>>(64, 64, g2, e2);

    conv3x3<64, 128, true, false, true><<<dim3(4,16,BB*8), blk>>>(
        y2, w3, b3, aff + 64, nullptr, stats + 192, gath, nxy);
    finalize_aff<<<1, 128>>>(128, 192, g3, e3);

    tail_kernel<<<(3528 + 1024 + 255)/256, 256>>>(image, axy, pxy, nxy, outp);
}

// round 9
// speedup vs baseline: 1.4781x; 1.1268x over previous
#include <cuda_runtime.h>
#include <cstdint>

#define BB 8
#define HH 256
#define WW 256
#define NPIX (BB*HH*WW)

// ---------------- device scratch ----------------
__device__ float g_y1[BB*32*HH*WW];            // conv1 out: raw, then normalized in place
__device__ float g_y2[(size_t)BB*64*HH*WW];    // conv2 out: raw, then normalized in place
__device__ float g_stats[2*(32+64+128)];
__device__ float g_aff[2*(32+64+128)];
__device__ float g_gath[BB*128];

__global__ void zero_stats() {
    int i = blockIdx.x*blockDim.x + threadIdx.x;
    if (i < 448) g_stats[i] = 0.f;
}

// packed f32x2 helpers
__device__ __forceinline__ unsigned long long pack2(float lo, float hi) {
    unsigned long long r;
    asm("mov.b64 %0, {%1, %2};" : "=l"(r) : "f"(lo), "f"(hi));
    return r;
}
__device__ __forceinline__ void unpack2(unsigned long long v, float& lo, float& hi) {
    asm("mov.b64 {%0, %1}, %2;" : "=f"(lo), "=f"(hi) : "l"(v));
}
__device__ __forceinline__ void fma2(unsigned long long& d,
                                     unsigned long long a, unsigned long long b) {
    asm("fma.rn.f32x2 %0, %1, %2, %0;" : "+l"(d) : "l"(a), "l"(b));
}

// ---------------- fused conv3x3 (cout-pair f32x2, 4 px/thread, cp.async pipeline) ----
// 256 threads. Output tile 64(W) x 16(H) x 16 couts. Input is PRE-NORMALIZED.
// Thread (tx,ty): 4 adjacent cols [4tx,4tx+4) in row ty, all 16 couts.
template<int CIN, int COUT, bool WRITE_OUT, bool GATHER>
__global__ __launch_bounds__(256, 2)
void conv3x3(const float* __restrict__ in,
             const float* __restrict__ w,      // [COUT,CIN,3,3]
             const float* __restrict__ bias,
             float* __restrict__ out,
             float* __restrict__ stats,
             float* __restrict__ gath,
             const int* __restrict__ nxy)
{
    __shared__ __align__(16) float s_w[CIN*9*16];     // [ci][k][o]
    __shared__ __align__(16) float s_in[2][18][66];   // 64+2 halo, double buffered
    __shared__ float s_red[2][16][8];

    const int tid = threadIdx.x;
    const int tx = tid & 15;
    const int ty = tid >> 4;
    const int tileX = blockIdx.x * 64, tileY = blockIdx.y * 16;
    const int ng  = COUT / 16;
    const int cog = blockIdx.z % ng;
    const int b   = blockIdx.z / ng;
    const int co0 = cog * 16;

    // ---- preload all weights transposed to [ci][k][o]
    for (int e = tid; e < CIN*144; e += 256) {
        int ci  = e / 144;
        int rem = e - ci*144;
        int o   = rem / 9;
        int k   = rem - o*9;
        s_w[(ci*9 + k)*16 + o] = w[((co0 + o)*CIN + ci)*9 + k];
    }

    // ---- async tile copy: fire-and-forget GMEM->SMEM (zero-fill OOB halo)
    auto copy_tile = [&](int ci, int buf) {
        const float* inp = in + ((size_t)(b*CIN + ci))*HH*WW;
        #pragma unroll
        for (int it = 0; it < 5; ++it) {
            int e = tid + it*256;
            if (e < 18*66) {
                int r = e / 66, c = e - r*66;
                int gy = tileY + r - 1, gx = tileX + c - 1;
                bool ok = (unsigned)gy < (unsigned)HH && (unsigned)gx < (unsigned)WW;
                const float* src = ok ? &inp[gy*WW + gx] : inp;
                uint32_t dst = (uint32_t)__cvta_generic_to_shared(&s_in[buf][r][c]);
                int sz = ok ? 4 : 0;   // src-size 0 -> 4 bytes zero-filled
                asm volatile("cp.async.ca.shared.global [%0], [%1], 4, %2;"
                             :: "r"(dst), "l"(src), "r"(sz) : "memory");
            }
        }
    };

    // acc[pr][px]: cout pair pr (couts 2pr,2pr+1), pixel px (col 4tx+px)
    unsigned long long acc[8][4];
    #pragma unroll
    for (int pr = 0; pr < 8; ++pr)
        #pragma unroll
        for (int px = 0; px < 4; ++px) acc[pr][px] = 0ull;

    copy_tile(0, 0);
    asm volatile("cp.async.commit_group;" ::: "memory");
    asm volatile("cp.async.wait_group 0;" ::: "memory");
    __syncthreads();   // covers s_w writes + first tile

    for (int ci = 0; ci < CIN; ++ci) {
        const int buf = ci & 1;
        const bool more = (ci + 1 < CIN);
        if (more) {
            copy_tile(ci + 1, buf ^ 1);   // async into the other buffer
            asm volatile("cp.async.commit_group;" ::: "memory");
        }

        #pragma unroll
        for (int r = 0; r < 3; ++r) {
            float2 xa = *reinterpret_cast<const float2*>(&s_in[buf][ty + r][4*tx]);
            float2 xb = *reinterpret_cast<const float2*>(&s_in[buf][ty + r][4*tx + 2]);
            float2 xc = *reinterpret_cast<const float2*>(&s_in[buf][ty + r][4*tx + 4]);
            unsigned long long X[6];
            X[0] = pack2(xa.x, xa.x); X[1] = pack2(xa.y, xa.y);
            X[2] = pack2(xb.x, xb.x); X[3] = pack2(xb.y, xb.y);
            X[4] = pack2(xc.x, xc.x); X[5] = pack2(xc.y, xc.y);

            #pragma unroll
            for (int c = 0; c < 3; ++c) {
                const int k = 3*r + c;
                const float* wq = &s_w[(ci*9 + k)*16];
                unsigned long long W8[8];
                asm volatile("ld.shared.v2.b64 {%0, %1}, [%2];"
                    : "=l"(W8[0]), "=l"(W8[1])
                    : "r"((unsigned)__cvta_generic_to_shared(wq)));
                asm volatile("ld.shared.v2.b64 {%0, %1}, [%2];"
                    : "=l"(W8[2]), "=l"(W8[3])
                    : "r"((unsigned)__cvta_generic_to_shared(wq + 4)));
                asm volatile("ld.shared.v2.b64 {%0, %1}, [%2];"
                    : "=l"(W8[4]), "=l"(W8[5])
                    : "r"((unsigned)__cvta_generic_to_shared(wq + 8)));
                asm volatile("ld.shared.v2.b64 {%0, %1}, [%2];"
                    : "=l"(W8[6]), "=l"(W8[7])
                    : "r"((unsigned)__cvta_generic_to_shared(wq + 12)));

                #pragma unroll
                for (int pr = 0; pr < 8; ++pr)
                    #pragma unroll
                    for (int px = 0; px < 4; ++px)
                        fma2(acc[pr][px], W8[pr], X[c + px]);
            }
        }
        if (more) asm volatile("cp.async.wait_group 0;" ::: "memory");
        __syncthreads();   // all reads of buf done; next tile visible to all
    }

    // ---- unpack + bias
    float a[16][4];
    #pragma unroll
    for (int pr = 0; pr < 8; ++pr)
        #pragma unroll
        for (int px = 0; px < 4; ++px)
            unpack2(acc[pr][px], a[2*pr][px], a[2*pr + 1][px]);
    #pragma unroll
    for (int o = 0; o < 16; ++o) {
        float bv = bias[co0 + o];
        #pragma unroll
        for (int px = 0; px < 4; ++px) a[o][px] += bv;
    }

    const int y   = tileY + ty;
    const int x0b = tileX + 4*tx;

    if (WRITE_OUT) {
        #pragma unroll
        for (int o = 0; o < 16; ++o) {
            *reinterpret_cast<float4*>(
                &out[(((size_t)b*COUT + co0 + o)*HH + y)*WW + x0b]) =
                make_float4(a[o][0], a[o][1], a[o][2], a[o][3]);
        }
    }

    if (GATHER) {
        const int ny = nxy[b*64 + 62];
        const int nx = nxy[b*64 + 63];
        if (y == ny && nx >= x0b && nx < x0b + 4) {
            #pragma unroll
            for (int o = 0; o < 16; ++o)
                gath[b*COUT + co0 + o] = a[o][nx - x0b];
        }
    }

    // ---- BN stats: warp shuffle then one atomicAdd per channel
    const int lane = tid & 31, wid = tid >> 5;
    #pragma unroll
    for (int o = 0; o < 16; ++o) {
        float s = 0.f, ss = 0.f;
        #pragma unroll
        for (int px = 0; px < 4; ++px) { s += a[o][px]; ss += a[o][px]*a[o][px]; }
        #pragma unroll
        for (int off = 16; off; off >>= 1) {
            s  += __shfl_down_sync(0xffffffffu, s,  off);
            ss += __shfl_down_sync(0xffffffffu, ss, off);
        }
        if (lane == 0) { s_red[0][o][wid] = s; s_red[1][o][wid] = ss; }
    }
    __syncthreads();
    if (tid < 16) {
        float s = 0.f, ss = 0.f;
        #pragma unroll
        for (int k = 0; k < 8; ++k) { s += s_red[0][tid][k]; ss += s_red[1][tid][k]; }
        atomicAdd(&stats[co0 + tid],        s);
        atomicAdd(&stats[COUT + co0 + tid], ss);
    }
}

// ---------------- BN finalize ----------------
__global__ void finalize_aff(int C, int off,
                             const float* __restrict__ gamma,
                             const float* __restrict__ beta)
{
    int c = threadIdx.x;
    if (c < C) {
        const float n = (float)NPIX;
        float m = g_stats[off + c] / n;
        float v = g_stats[off + C + c] / n - m*m;
        float a = gamma[c] * rsqrtf(v + 1e-5f);
        g_aff[off + c]     = a;
        g_aff[off + C + c] = beta[c] - m*a;
    }
}

// ---------------- in-place normalize: y = lrelu(scale[c]*y + shift[c]) ----------------
// CLOG2: log2 of per-channel float4 count (HH*WW/4 = 16384 = 2^14)
template<int C>
__global__ __launch_bounds__(256)
void normalize_k(float* __restrict__ y, const float* __restrict__ aff)
{
    int i = blockIdx.x*blockDim.x + threadIdx.x;   // float4 index
    int c = (i >> 14) & (C - 1);
    float sA = aff[c], sB = aff[C + c];
    float4 v = reinterpret_cast<float4*>(y)[i];
    v.x = fmaf(sA, v.x, sB); v.x = (v.x > 0.f) ? v.x : 0.01f*v.x;
    v.y = fmaf(sA, v.y, sB); v.y = (v.y > 0.f) ? v.y : 0.01f*v.y;
    v.z = fmaf(sA, v.z, sB); v.z = (v.z > 0.f) ? v.z : 0.01f*v.z;
    v.w = fmaf(sA, v.w, sB); v.w = (v.w > 0.f) ? v.w : 0.01f*v.w;
    reinterpret_cast<float4*>(y)[i] = v;
}

// ---------------- tail ----------------
__global__ void tail_kernel(const float* __restrict__ image,
                            const int* __restrict__ axy,
                            const int* __restrict__ pxy,
                            const int* __restrict__ nxy,
                            float* __restrict__ out)
{
    int i = blockIdx.x*blockDim.x + threadIdx.x;
    if (i < 3528) {
        int which = i / 1176;
        int rem   = i % 1176;
        int b  = rem / 147;
        int r2 = rem % 147;
        int c  = r2 / 49;
        int p  = r2 % 49;
        int pi = p / 7, pj = p % 7;
        const int* xy = (which == 0) ? axy : (which == 1) ? pxy : nxy;
        int y0 = xy[b*64 + 62] - 3;
        int x0 = xy[b*64 + 63] - 3;
        out[i] = image[((b*3 + c)*HH + (y0 + pi))*WW + (x0 + pj)];
    } else if (i < 3528 + 1024) {
        int j = i - 3528;
        int c = j & 127;
        float v = fmaf(g_aff[192 + c], g_gath[j], g_aff[192 + 128 + c]);
        out[i] = (v > 0.f) ? v : 0.01f*v;
    }
}

// ---------------- launch ----------------
extern "C" void kernel_launch(void* const* d_in, const int* in_sizes, int n_in,
                              void* d_out, int out_size)
{
    const float* image = (const float*)d_in[0];
    const int*   axy   = (const int*)  d_in[1];
    const int*   pxy   = (const int*)  d_in[2];
    const int*   nxy   = (const int*)  d_in[3];
    const float* w1 = (const float*)d_in[4];
    const float* b1 = (const float*)d_in[5];
    const float* g1 = (const float*)d_in[6];
    const float* e1 = (const float*)d_in[7];
    const float* w2 = (const float*)d_in[8];
    const float* b2 = (const float*)d_in[9];
    const float* g2 = (const float*)d_in[10];
    const float* e2 = (const float*)d_in[11];
    const float* w3 = (const float*)d_in[12];
    const float* b3 = (const float*)d_in[13];
    const float* g3 = (const float*)d_in[14];
    const float* e3 = (const float*)d_in[15];
    float* outp = (float*)d_out;

    float *y1, *y2, *stats, *aff, *gath;
    cudaGetSymbolAddress((void**)&y1,    g_y1);
    cudaGetSymbolAddress((void**)&y2,    g_y2);
    cudaGetSymbolAddress((void**)&stats, g_stats);
    cudaGetSymbolAddress((void**)&aff,   g_aff);
    cudaGetSymbolAddress((void**)&gath,  g_gath);

    dim3 blk(256);

    zero_stats<<<2, 256>>>();

    // conv1: image -> raw y1 + stats
    conv3x3<3, 32, true, false><<<dim3(4,16,BB*2), blk>>>(
        image, w1, b1, y1, stats + 0, nullptr, nullptr);
    finalize_aff<<<1, 32>>>(32, 0, g1, e1);
    normalize_k<32><<<(BB*32*HH*WW/4)/256, 256>>>(y1, aff + 0);

    // conv2: normalized y1 -> raw y2 + stats
    conv3x3<32, 64, true, false><<<dim3(4,16,BB*4), blk>>>(
        y1, w2, b2, y2, stats + 64, nullptr, nullptr);
    finalize_aff<<<1, 64>>>(64, 64, g2, e2);
    normalize_k<64><<<(BB*64*HH*WW/4)/256, 256>>>(y2, aff + 64);

    // conv3: normalized y2 -> stats + gathered pixels (no store)
    conv3x3<64, 128, false, true><<<dim3(4,16,BB*8), blk>>>(
        y2, w3, b3, nullptr, stats + 192, gath, nxy);
    finalize_aff<<<1, 128>>>(128, 192, g3, e3);

    tail_kernel<<<(3528 + 1024 + 255)/256, 256>>>(image, axy, pxy, nxy, outp);
}

// round 14
// speedup vs baseline: 2.1643x; 1.4642x over previous
#include <cuda_runtime.h>
#include <cstdint>

#define BB 8
#define HH 256
#define WW 256
#define NPIX (BB*HH*WW)

// ---------------- device scratch ----------------
__device__ float g_y1[BB*32*HH*WW];            // conv1 out: raw -> normalized fp32
__device__ float g_y2[(size_t)BB*64*HH*WW];    // conv2 out: raw -> normalized tf32-rounded
__device__ float g_stats[2*(32+64+128)];
__device__ float g_aff[2*(32+64+128)];
__device__ float g_gath[BB*128];

__global__ void zero_stats() {
    int i = blockIdx.x*blockDim.x + threadIdx.x;
    if (i < 448) g_stats[i] = 0.f;
}

// packed f32x2 helpers (conv1/conv2 FFMA2 path)
__device__ __forceinline__ unsigned long long pack2(float lo, float hi) {
    unsigned long long r;
    asm("mov.b64 %0, {%1, %2};" : "=l"(r) : "f"(lo), "f"(hi));
    return r;
}
__device__ __forceinline__ void unpack2(unsigned long long v, float& lo, float& hi) {
    asm("mov.b64 {%0, %1}, %2;" : "=f"(lo), "=f"(hi) : "l"(v));
}
__device__ __forceinline__ void fma2(unsigned long long& d,
                                     unsigned long long a, unsigned long long b) {
    asm("fma.rn.f32x2 %0, %1, %2, %0;" : "+l"(d) : "l"(a), "l"(b));
}
__device__ __forceinline__ uint32_t f2tf32(float x) {
    uint32_t u;
    asm("cvt.rna.tf32.f32 %0, %1;" : "=r"(u) : "f"(x));
    return u;
}

// ================= conv1/conv2: FFMA2 kernel (unchanged from R9) =================
template<int CIN, int COUT, bool WRITE_OUT, bool GATHER>
__global__ __launch_bounds__(256, 2)
void conv3x3(const float* __restrict__ in,
             const float* __restrict__ w,
             const float* __restrict__ bias,
             float* __restrict__ out,
             float* __restrict__ stats,
             float* __restrict__ gath,
             const int* __restrict__ nxy)
{
    __shared__ __align__(16) float s_w[CIN*9*16];
    __shared__ __align__(16) float s_in[2][18][66];
    __shared__ float s_red[2][16][8];

    const int tid = threadIdx.x;
    const int tx = tid & 15;
    const int ty = tid >> 4;
    const int tileX = blockIdx.x * 64, tileY = blockIdx.y * 16;
    const int ng  = COUT / 16;
    const int cog = blockIdx.z % ng;
    const int b   = blockIdx.z / ng;
    const int co0 = cog * 16;

    for (int e = tid; e < CIN*144; e += 256) {
        int ci  = e / 144;
        int rem = e - ci*144;
        int o   = rem / 9;
        int k   = rem - o*9;
        s_w[(ci*9 + k)*16 + o] = w[((co0 + o)*CIN + ci)*9 + k];
    }

    auto copy_tile = [&](int ci, int buf) {
        const float* inp = in + ((size_t)(b*CIN + ci))*HH*WW;
        #pragma unroll
        for (int it = 0; it < 5; ++it) {
            int e = tid + it*256;
            if (e < 18*66) {
                int r = e / 66, c = e - r*66;
                int gy = tileY + r - 1, gx = tileX + c - 1;
                bool ok = (unsigned)gy < (unsigned)HH && (unsigned)gx < (unsigned)WW;
                const float* src = ok ? &inp[gy*WW + gx] : inp;
                uint32_t dst = (uint32_t)__cvta_generic_to_shared(&s_in[buf][r][c]);
                int sz = ok ? 4 : 0;
                asm volatile("cp.async.ca.shared.global [%0], [%1], 4, %2;"
                             :: "r"(dst), "l"(src), "r"(sz) : "memory");
            }
        }
    };

    unsigned long long acc[8][4];
    #pragma unroll
    for (int pr = 0; pr < 8; ++pr)
        #pragma unroll
        for (int px = 0; px < 4; ++px) acc[pr][px] = 0ull;

    copy_tile(0, 0);
    asm volatile("cp.async.commit_group;" ::: "memory");
    asm volatile("cp.async.wait_group 0;" ::: "memory");
    __syncthreads();

    for (int ci = 0; ci < CIN; ++ci) {
        const int buf = ci & 1;
        const bool more = (ci + 1 < CIN);
        if (more) {
            copy_tile(ci + 1, buf ^ 1);
            asm volatile("cp.async.commit_group;" ::: "memory");
        }

        #pragma unroll
        for (int r = 0; r < 3; ++r) {
            float2 xa = *reinterpret_cast<const float2*>(&s_in[buf][ty + r][4*tx]);
            float2 xb = *reinterpret_cast<const float2*>(&s_in[buf][ty + r][4*tx + 2]);
            float2 xc = *reinterpret_cast<const float2*>(&s_in[buf][ty + r][4*tx + 4]);
            unsigned long long X[6];
            X[0] = pack2(xa.x, xa.x); X[1] = pack2(xa.y, xa.y);
            X[2] = pack2(xb.x, xb.x); X[3] = pack2(xb.y, xb.y);
            X[4] = pack2(xc.x, xc.x); X[5] = pack2(xc.y, xc.y);

            #pragma unroll
            for (int c = 0; c < 3; ++c) {
                const int k = 3*r + c;
                const float* wq = &s_w[(ci*9 + k)*16];
                unsigned long long W8[8];
                asm volatile("ld.shared.v2.b64 {%0, %1}, [%2];"
                    : "=l"(W8[0]), "=l"(W8[1])
                    : "r"((unsigned)__cvta_generic_to_shared(wq)));
                asm volatile("ld.shared.v2.b64 {%0, %1}, [%2];"
                    : "=l"(W8[2]), "=l"(W8[3])
                    : "r"((unsigned)__cvta_generic_to_shared(wq + 4)));
                asm volatile("ld.shared.v2.b64 {%0, %1}, [%2];"
                    : "=l"(W8[4]), "=l"(W8[5])
                    : "r"((unsigned)__cvta_generic_to_shared(wq + 8)));
                asm volatile("ld.shared.v2.b64 {%0, %1}, [%2];"
                    : "=l"(W8[6]), "=l"(W8[7])
                    : "r"((unsigned)__cvta_generic_to_shared(wq + 12)));

                #pragma unroll
                for (int pr = 0; pr < 8; ++pr)
                    #pragma unroll
                    for (int px = 0; px < 4; ++px)
                        fma2(acc[pr][px], W8[pr], X[c + px]);
            }
        }
        if (more) asm volatile("cp.async.wait_group 0;" ::: "memory");
        __syncthreads();
    }

    float a[16][4];
    #pragma unroll
    for (int pr = 0; pr < 8; ++pr)
        #pragma unroll
        for (int px = 0; px < 4; ++px)
            unpack2(acc[pr][px], a[2*pr][px], a[2*pr + 1][px]);
    #pragma unroll
    for (int o = 0; o < 16; ++o) {
        float bv = bias[co0 + o];
        #pragma unroll
        for (int px = 0; px < 4; ++px) a[o][px] += bv;
    }

    const int y   = tileY + ty;
    const int x0b = tileX + 4*tx;

    if (WRITE_OUT) {
        #pragma unroll
        for (int o = 0; o < 16; ++o) {
            *reinterpret_cast<float4*>(
                &out[(((size_t)b*COUT + co0 + o)*HH + y)*WW + x0b]) =
                make_float4(a[o][0], a[o][1], a[o][2], a[o][3]);
        }
    }

    if (GATHER) {
        const int ny = nxy[b*64 + 62];
        const int nx = nxy[b*64 + 63];
        if (y == ny && nx >= x0b && nx < x0b + 4) {
            #pragma unroll
            for (int o = 0; o < 16; ++o)
                gath[b*COUT + co0 + o] = a[o][nx - x0b];
        }
    }

    const int lane = tid & 31, wid = tid >> 5;
    #pragma unroll
    for (int o = 0; o < 16; ++o) {
        float s = 0.f, ss = 0.f;
        #pragma unroll
        for (int px = 0; px < 4; ++px) { s += a[o][px]; ss += a[o][px]*a[o][px]; }
        #pragma unroll
        for (int off = 16; off; off >>= 1) {
            s  += __shfl_down_sync(0xffffffffu, s,  off);
            ss += __shfl_down_sync(0xffffffffu, ss, off);
        }
        if (lane == 0) { s_red[0][o][wid] = s; s_red[1][o][wid] = ss; }
    }
    __syncthreads();
    if (tid < 16) {
        float s = 0.f, ss = 0.f;
        #pragma unroll
        for (int k = 0; k < 8; ++k) { s += s_red[0][tid][k]; ss += s_red[1][tid][k]; }
        atomicAdd(&stats[co0 + tid],        s);
        atomicAdd(&stats[COUT + co0 + tid], ss);
    }
}

// ================= conv3: implicit-GEMM tf32 mma.sync =================
// 256 threads = 8 warps. Tile: 64(W) x 16(H) px, 16 couts. Warp w: rows 2w,2w+1.
// K = 64ci x 9taps via 8 chunks of 8 ci; m16n8k8 tf32.
// smem layout (words): s_w [0,9216)  [chunk][tap][k8][m16]
//                      s_in [9216, 9216+2*8*1304)  per ci: 18 rows x 72 words, CSTR=1304
//                      s_red [30080, +256)
#define CSTR 1304
#define BSTR (8*CSTR)
__global__ __launch_bounds__(256)
void conv3_mma(const float* __restrict__ in,     // normalized tf32-rounded y2 [8,64,256,256]
               const float* __restrict__ w,      // [128,64,3,3] fp32
               const float* __restrict__ bias,   // [128]
               float* __restrict__ stats,        // [sum128, sumsq128]
               float* __restrict__ gath,
               const int* __restrict__ nxy)
{
    extern __shared__ float sm[];
    float* s_w  = sm;
    float* s_in = sm + 9216;
    float* s_red = sm + 9216 + 2*BSTR;    // [2][16][8]

    const int tid  = threadIdx.x;
    const int lane = tid & 31;
    const int warp = tid >> 5;
    const int qr   = lane >> 2;     // A row group / B col group
    const int qk   = lane & 3;      // A/B k group
    const int tileX = blockIdx.x * 64, tileY = blockIdx.y * 16;
    const int b   = blockIdx.z >> 3;
    const int co0 = (blockIdx.z & 7) * 16;

    // ---- preload + tf32-convert weights: [chunk][tap][k][m]
    for (int e = tid; e < 9216; e += 256) {
        int m   = e & 15;
        int k   = (e >> 4) & 7;
        int ct  = e >> 7;            // chunk*9 + tap
        int chunk = ct / 9;
        int tap   = ct - chunk*9;
        int ci    = chunk*8 + k;
        float wv = w[(co0 + m)*576 + ci*9 + tap];
        s_w[e] = __uint_as_float(f2tf32(wv));
    }

    // ---- async halo copy for one 8-ci chunk: per ci 18 rows x 18 16B-granules
    auto copy_chunk = [&](int chunk, int buf) {
        const float* base = in + ((size_t)(b*64 + chunk*8))*(HH*WW);
        #pragma unroll
        for (int it = 0; it < 11; ++it) {
            int e = tid + it*256;
            if (e < 2592) {
                int ci  = e / 324;
                int rem = e - ci*324;
                int r   = rem / 18;
                int g   = rem - r*18;
                int gy  = tileY + r - 1;
                int gxw = tileX - 4 + 4*g;
                bool ok = (gy >= 0) && (gy < HH) && (gxw >= 0) && (gxw + 3 < WW);
                const float* src = ok ? (base + ci*(HH*WW) + gy*WW + gxw) : base;
                uint32_t dst = (uint32_t)__cvta_generic_to_shared(
                    &s_in[buf*BSTR + ci*CSTR + r*72 + 4*g]);
                int sz = ok ? 16 : 0;
                asm volatile("cp.async.ca.shared.global [%0], [%1], 16, %2;"
                             :: "r"(dst), "l"(src), "r"(sz) : "memory");
            }
        }
    };

    float d[64];
    #pragma unroll
    for (int i = 0; i < 64; ++i) d[i] = 0.f;

    copy_chunk(0, 0);
    asm volatile("cp.async.commit_group;" ::: "memory");
    asm volatile("cp.async.wait_group 0;" ::: "memory");
    __syncthreads();

    for (int chunk = 0; chunk < 8; ++chunk) {
        const int buf = chunk & 1;
        const bool more = (chunk + 1 < 8);
        if (more) {
            copy_chunk(chunk + 1, buf ^ 1);
            asm volatile("cp.async.commit_group;" ::: "memory");
        }

        const float* sib = s_in + buf*BSTR;

        #pragma unroll
        for (int tap = 0; tap < 9; ++tap) {
            const int dy = tap / 3, dx = tap - 3*dy;
            // A frag
            const float* wq = s_w + ((chunk*9 + tap)*8 + qk)*16 + qr;
            uint32_t a0 = __float_as_uint(wq[0]);
            uint32_t a1 = __float_as_uint(wq[8]);
            uint32_t a2 = __float_as_uint(wq[64]);
            uint32_t a3 = __float_as_uint(wq[72]);

            #pragma unroll
            for (int jr = 0; jr < 2; ++jr) {
                const float* rowp = sib + (2*warp + jr + dy)*72 + 3 + dx + qr;
                #pragma unroll
                for (int jc = 0; jc < 8; ++jc) {
                    uint32_t b0 = __float_as_uint(rowp[qk*CSTR + 8*jc]);
                    uint32_t b1 = __float_as_uint(rowp[(qk + 4)*CSTR + 8*jc]);
                    float* dd = &d[4*(jr*8 + jc)];
                    asm("mma.sync.aligned.m16n8k8.row.col.f32.tf32.tf32.f32 "
                        "{%0,%1,%2,%3}, {%4,%5,%6,%7}, {%8,%9}, {%0,%1,%2,%3};"
                        : "+f"(dd[0]), "+f"(dd[1]), "+f"(dd[2]), "+f"(dd[3])
                        : "r"(a0), "r"(a1), "r"(a2), "r"(a3), "r"(b0), "r"(b1));
                }
            }
        }
        if (more) asm volatile("cp.async.wait_group 0;" ::: "memory");
        __syncthreads();
    }

    // ---- bias
    const float blo = bias[co0 + qr];
    const float bhi = bias[co0 + qr + 8];
    #pragma unroll
    for (int j = 0; j < 16; ++j) {
        d[4*j+0] += blo; d[4*j+1] += blo;
        d[4*j+2] += bhi; d[4*j+3] += bhi;
    }

    // ---- gather (raw conv3 at target pixel)
    {
        const int ny = nxy[b*64 + 62];
        const int nx = nxy[b*64 + 63];
        if (ny >= tileY && ny < tileY + 16 && nx >= tileX && nx < tileX + 64) {
            int lr = ny - tileY, lc = nx - tileX;
            if ((lr >> 1) == warp && (lane & 3) == ((lc & 7) >> 1)) {
                int jt = (lr & 1)*8 + (lc >> 3);
                int sel = lc & 1;
                #pragma unroll
                for (int j = 0; j < 16; ++j) if (j == jt) {
                    gath[b*128 + co0 + qr]     = d[4*j + sel];
                    gath[b*128 + co0 + qr + 8] = d[4*j + 2 + sel];
                }
            }
        }
    }

    // ---- BN stats
    float slo = 0.f, sslo = 0.f, shi = 0.f, sshi = 0.f;
    #pragma unroll
    for (int j = 0; j < 16; ++j) {
        slo  += d[4*j+0] + d[4*j+1];
        sslo += d[4*j+0]*d[4*j+0] + d[4*j+1]*d[4*j+1];
        shi  += d[4*j+2] + d[4*j+3];
        sshi += d[4*j+2]*d[4*j+2] + d[4*j+3]*d[4*j+3];
    }
    slo  += __shfl_down_sync(0xffffffffu, slo,  2);
    slo  += __shfl_down_sync(0xffffffffu, slo,  1);
    sslo += __shfl_down_sync(0xffffffffu, sslo, 2);
    sslo += __shfl_down_sync(0xffffffffu, sslo, 1);
    shi  += __shfl_down_sync(0xffffffffu, shi,  2);
    shi  += __shfl_down_sync(0xffffffffu, shi,  1);
    sshi += __shfl_down_sync(0xffffffffu, sshi, 2);
    sshi += __shfl_down_sync(0xffffffffu, sshi, 1);
    if ((lane & 3) == 0) {
        s_red[(0*16 + qr)*8     + warp] = slo;
        s_red[(0*16 + qr + 8)*8 + warp] = shi;
        s_red[(1*16 + qr)*8 + 128 + warp - 128] = 0.f; // placeholder avoided below
    }
    // store sumsq separately (second half of s_red)
    if ((lane & 3) == 0) {
        s_red[128 + (qr)*8     + warp] = sslo;
        s_red[128 + (qr + 8)*8 + warp] = sshi;
    }
    __syncthreads();
    if (tid < 16) {
        float s = 0.f, ss = 0.f;
        #pragma unroll
        for (int k = 0; k < 8; ++k) { s += s_red[tid*8 + k]; ss += s_red[128 + tid*8 + k]; }
        atomicAdd(&stats[co0 + tid],       s);
        atomicAdd(&stats[128 + co0 + tid], ss);
    }
}

// ---------------- BN finalize ----------------
__global__ void finalize_aff(int C, int off,
                             const float* __restrict__ gamma,
                             const float* __restrict__ beta)
{
    int c = threadIdx.x;
    if (c < C) {
        const float n = (float)NPIX;
        float m = g_stats[off + c] / n;
        float v = g_stats[off + C + c] / n - m*m;
        float a = gamma[c] * rsqrtf(v + 1e-5f);
        g_aff[off + c]     = a;
        g_aff[off + C + c] = beta[c] - m*a;
    }
}

// ---------------- in-place normalize (fp32 out, for y1) ----------------
template<int C>
__global__ __launch_bounds__(256)
void normalize_k(float* __restrict__ y, const float* __restrict__ aff)
{
    int i = blockIdx.x*blockDim.x + threadIdx.x;
    int c = (i >> 14) & (C - 1);
    float sA = aff[c], sB = aff[C + c];
    float4 v = reinterpret_cast<float4*>(y)[i];
    v.x = fmaf(sA, v.x, sB); v.x = (v.x > 0.f) ? v.x : 0.01f*v.x;
    v.y = fmaf(sA, v.y, sB); v.y = (v.y > 0.f) ? v.y : 0.01f*v.y;
    v.z = fmaf(sA, v.z, sB); v.z = (v.z > 0.f) ? v.z : 0.01f*v.z;
    v.w = fmaf(sA, v.w, sB); v.w = (v.w > 0.f) ? v.w : 0.01f*v.w;
    reinterpret_cast<float4*>(y)[i] = v;
}

// ---------------- normalize + tf32 round (for y2 -> conv3) ----------------
template<int C>
__global__ __launch_bounds__(256)
void normalize_tf32(float* __restrict__ y, const float* __restrict__ aff)
{
    int i = blockIdx.x*blockDim.x + threadIdx.x;
    int c = (i >> 14) & (C - 1);
    float sA = aff[c], sB = aff[C + c];
    float4 v = reinterpret_cast<float4*>(y)[i];
    v.x = fmaf(sA, v.x, sB); v.x = (v.x > 0.f) ? v.x : 0.01f*v.x;
    v.y = fmaf(sA, v.y, sB); v.y = (v.y > 0.f) ? v.y : 0.01f*v.y;
    v.z = fmaf(sA, v.z, sB); v.z = (v.z > 0.f) ? v.z : 0.01f*v.z;
    v.w = fmaf(sA, v.w, sB); v.w = (v.w > 0.f) ? v.w : 0.01f*v.w;
    v.x = __uint_as_float(f2tf32(v.x));
    v.y = __uint_as_float(f2tf32(v.y));
    v.z = __uint_as_float(f2tf32(v.z));
    v.w = __uint_as_float(f2tf32(v.w));
    reinterpret_cast<float4*>(y)[i] = v;
}

// ---------------- tail ----------------
__global__ void tail_kernel(const float* __restrict__ image,
                            const int* __restrict__ axy,
                            const int* __restrict__ pxy,
                            const int* __restrict__ nxy,
                            float* __restrict__ out)
{
    int i = blockIdx.x*blockDim.x + threadIdx.x;
    if (i < 3528) {
        int which = i / 1176;
        int rem   = i % 1176;
        int b  = rem / 147;
        int r2 = rem % 147;
        int c  = r2 / 49;
        int p  = r2 % 49;
        int pi = p / 7, pj = p % 7;
        const int* xy = (which == 0) ? axy : (which == 1) ? pxy : nxy;
        int y0 = xy[b*64 + 62] - 3;
        int x0 = xy[b*64 + 63] - 3;
        out[i] = image[((b*3 + c)*HH + (y0 + pi))*WW + (x0 + pj)];
    } else if (i < 3528 + 1024) {
        int j = i - 3528;
        int c = j & 127;
        float v = fmaf(g_aff[192 + c], g_gath[j], g_aff[192 + 128 + c]);
        out[i] = (v > 0.f) ? v : 0.01f*v;
    }
}

// ---------------- launch ----------------
extern "C" void kernel_launch(void* const* d_in, const int* in_sizes, int n_in,
                              void* d_out, int out_size)
{
    const float* image = (const float*)d_in[0];
    const int*   axy   = (const int*)  d_in[1];
    const int*   pxy   = (const int*)  d_in[2];
    const int*   nxy   = (const int*)  d_in[3];
    const float* w1 = (const float*)d_in[4];
    const float* b1 = (const float*)d_in[5];
    const float* g1 = (const float*)d_in[6];
    const float* e1 = (const float*)d_in[7];
    const float* w2 = (const float*)d_in[8];
    const float* b2 = (const float*)d_in[9];
    const float* g2 = (const float*)d_in[10];
    const float* e2 = (const float*)d_in[11];
    const float* w3 = (const float*)d_in[12];
    const float* b3 = (const float*)d_in[13];
    const float* g3 = (const float*)d_in[14];
    const float* e3 = (const float*)d_in[15];
    float* outp = (float*)d_out;

    float *y1, *y2, *stats, *aff, *gath;
    cudaGetSymbolAddress((void**)&y1,    g_y1);
    cudaGetSymbolAddress((void**)&y2,    g_y2);
    cudaGetSymbolAddress((void**)&stats, g_stats);
    cudaGetSymbolAddress((void**)&aff,   g_aff);
    cudaGetSymbolAddress((void**)&gath,  g_gath);

    const int SMEM3 = (9216 + 2*BSTR + 256) * 4;   // 121344 B
    cudaFuncSetAttribute(conv3_mma, cudaFuncAttributeMaxDynamicSharedMemorySize, SMEM3);

    dim3 blk(256);

    zero_stats<<<2, 256>>>();

    // conv1: image -> raw y1 + stats (fp32 FFMA2)
    conv3x3<3, 32, true, false><<<dim3(4,16,BB*2), blk>>>(
        image, w1, b1, y1, stats + 0, nullptr, nullptr);
    finalize_aff<<<1, 32>>>(32, 0, g1, e1);
    normalize_k<32><<<(BB*32*HH*WW/4)/256, 256>>>(y1, aff + 0);

    // conv2: normalized y1 -> raw y2 + stats (fp32 FFMA2)
    conv3x3<32, 64, true, false><<<dim3(4,16,BB*4), blk>>>(
        y1, w2, b2, y2, stats + 64, nullptr, nullptr);
    finalize_aff<<<1, 64>>>(64, 64, g2, e2);
    normalize_tf32<64><<<(BB*64*HH*WW/4)/256, 256>>>(y2, aff + 64);

    // conv3: tf32 mma implicit GEMM -> stats + gathered pixels
    conv3_mma<<<dim3(4,16,64), blk, SMEM3>>>(
        y2, w3, b3, stats + 192, gath, nxy);
    finalize_aff<<<1, 128>>>(128, 192, g3, e3);

    tail_kernel<<<(3528 + 1024 + 255)/256, 256>>>(image, axy, pxy, nxy, outp);
}

// round 15
// speedup vs baseline: 2.5736x; 1.1891x over previous
#include <cuda_runtime.h>
#include <cstdint>

#define BB 8
#define HH 256
#define WW 256
#define NPIX (BB*HH*WW)

// ---------------- device scratch ----------------
__device__ float g_y1[BB*32*HH*WW];            // conv1 out: raw -> normalized tf32-rounded
__device__ float g_y2[(size_t)BB*64*HH*WW];    // conv2 out: raw -> normalized tf32-rounded
__device__ float g_stats[2*(32+64+128)];
__device__ float g_aff[2*(32+64+128)];
__device__ float g_gath[BB*128];

__global__ void zero_stats() {
    int i = blockIdx.x*blockDim.x + threadIdx.x;
    if (i < 448) g_stats[i] = 0.f;
}

// packed f32x2 helpers (conv1 FFMA2 path)
__device__ __forceinline__ unsigned long long pack2(float lo, float hi) {
    unsigned long long r;
    asm("mov.b64 %0, {%1, %2};" : "=l"(r) : "f"(lo), "f"(hi));
    return r;
}
__device__ __forceinline__ void unpack2(unsigned long long v, float& lo, float& hi) {
    asm("mov.b64 {%0, %1}, %2;" : "=f"(lo), "=f"(hi) : "l"(v));
}
__device__ __forceinline__ void fma2(unsigned long long& d,
                                     unsigned long long a, unsigned long long b) {
    asm("fma.rn.f32x2 %0, %1, %2, %0;" : "+l"(d) : "l"(a), "l"(b));
}
__device__ __forceinline__ uint32_t f2tf32(float x) {
    uint32_t u;
    asm("cvt.rna.tf32.f32 %0, %1;" : "=r"(u) : "f"(x));
    return u;
}

// ================= conv1: FFMA2 kernel (CIN=3) =================
template<int CIN, int COUT>
__global__ __launch_bounds__(256, 2)
void conv3x3(const float* __restrict__ in,
             const float* __restrict__ w,
             const float* __restrict__ bias,
             float* __restrict__ out,
             float* __restrict__ stats)
{
    __shared__ __align__(16) float s_w[CIN*9*16];
    __shared__ __align__(16) float s_in[2][18][66];
    __shared__ float s_red[2][16][8];

    const int tid = threadIdx.x;
    const int tx = tid & 15;
    const int ty = tid >> 4;
    const int tileX = blockIdx.x * 64, tileY = blockIdx.y * 16;
    const int ng  = COUT / 16;
    const int cog = blockIdx.z % ng;
    const int b   = blockIdx.z / ng;
    const int co0 = cog * 16;

    for (int e = tid; e < CIN*144; e += 256) {
        int ci  = e / 144;
        int rem = e - ci*144;
        int o   = rem / 9;
        int k   = rem - o*9;
        s_w[(ci*9 + k)*16 + o] = w[((co0 + o)*CIN + ci)*9 + k];
    }

    auto copy_tile = [&](int ci, int buf) {
        const float* inp = in + ((size_t)(b*CIN + ci))*HH*WW;
        #pragma unroll
        for (int it = 0; it < 5; ++it) {
            int e = tid + it*256;
            if (e < 18*66) {
                int r = e / 66, c = e - r*66;
                int gy = tileY + r - 1, gx = tileX + c - 1;
                bool ok = (unsigned)gy < (unsigned)HH && (unsigned)gx < (unsigned)WW;
                const float* src = ok ? &inp[gy*WW + gx] : inp;
                uint32_t dst = (uint32_t)__cvta_generic_to_shared(&s_in[buf][r][c]);
                int sz = ok ? 4 : 0;
                asm volatile("cp.async.ca.shared.global [%0], [%1], 4, %2;"
                             :: "r"(dst), "l"(src), "r"(sz) : "memory");
            }
        }
    };

    unsigned long long acc[8][4];
    #pragma unroll
    for (int pr = 0; pr < 8; ++pr)
        #pragma unroll
        for (int px = 0; px < 4; ++px) acc[pr][px] = 0ull;

    copy_tile(0, 0);
    asm volatile("cp.async.commit_group;" ::: "memory");
    asm volatile("cp.async.wait_group 0;" ::: "memory");
    __syncthreads();

    for (int ci = 0; ci < CIN; ++ci) {
        const int buf = ci & 1;
        const bool more = (ci + 1 < CIN);
        if (more) {
            copy_tile(ci + 1, buf ^ 1);
            asm volatile("cp.async.commit_group;" ::: "memory");
        }

        #pragma unroll
        for (int r = 0; r < 3; ++r) {
            float2 xa = *reinterpret_cast<const float2*>(&s_in[buf][ty + r][4*tx]);
            float2 xb = *reinterpret_cast<const float2*>(&s_in[buf][ty + r][4*tx + 2]);
            float2 xc = *reinterpret_cast<const float2*>(&s_in[buf][ty + r][4*tx + 4]);
            unsigned long long X[6];
            X[0] = pack2(xa.x, xa.x); X[1] = pack2(xa.y, xa.y);
            X[2] = pack2(xb.x, xb.x); X[3] = pack2(xb.y, xb.y);
            X[4] = pack2(xc.x, xc.x); X[5] = pack2(xc.y, xc.y);

            #pragma unroll
            for (int c = 0; c < 3; ++c) {
                const int k = 3*r + c;
                const float* wq = &s_w[(ci*9 + k)*16];
                unsigned long long W8[8];
                asm volatile("ld.shared.v2.b64 {%0, %1}, [%2];"
                    : "=l"(W8[0]), "=l"(W8[1])
                    : "r"((unsigned)__cvta_generic_to_shared(wq)));
                asm volatile("ld.shared.v2.b64 {%0, %1}, [%2];"
                    : "=l"(W8[2]), "=l"(W8[3])
                    : "r"((unsigned)__cvta_generic_to_shared(wq + 4)));
                asm volatile("ld.shared.v2.b64 {%0, %1}, [%2];"
                    : "=l"(W8[4]), "=l"(W8[5])
                    : "r"((unsigned)__cvta_generic_to_shared(wq + 8)));
                asm volatile("ld.shared.v2.b64 {%0, %1}, [%2];"
                    : "=l"(W8[6]), "=l"(W8[7])
                    : "r"((unsigned)__cvta_generic_to_shared(wq + 12)));

                #pragma unroll
                for (int pr = 0; pr < 8; ++pr)
                    #pragma unroll
                    for (int px = 0; px < 4; ++px)
                        fma2(acc[pr][px], W8[pr], X[c + px]);
            }
        }
        if (more) asm volatile("cp.async.wait_group 0;" ::: "memory");
        __syncthreads();
    }

    float a[16][4];
    #pragma unroll
    for (int pr = 0; pr < 8; ++pr)
        #pragma unroll
        for (int px = 0; px < 4; ++px)
            unpack2(acc[pr][px], a[2*pr][px], a[2*pr + 1][px]);
    #pragma unroll
    for (int o = 0; o < 16; ++o) {
        float bv = bias[co0 + o];
        #pragma unroll
        for (int px = 0; px < 4; ++px) a[o][px] += bv;
    }

    const int y   = tileY + ty;
    const int x0b = tileX + 4*tx;

    #pragma unroll
    for (int o = 0; o < 16; ++o) {
        *reinterpret_cast<float4*>(
            &out[(((size_t)b*COUT + co0 + o)*HH + y)*WW + x0b]) =
            make_float4(a[o][0], a[o][1], a[o][2], a[o][3]);
    }

    const int lane = tid & 31, wid = tid >> 5;
    #pragma unroll
    for (int o = 0; o < 16; ++o) {
        float s = 0.f, ss = 0.f;
        #pragma unroll
        for (int px = 0; px < 4; ++px) { s += a[o][px]; ss += a[o][px]*a[o][px]; }
        #pragma unroll
        for (int off = 16; off; off >>= 1) {
            s  += __shfl_down_sync(0xffffffffu, s,  off);
            ss += __shfl_down_sync(0xffffffffu, ss, off);
        }
        if (lane == 0) { s_red[0][o][wid] = s; s_red[1][o][wid] = ss; }
    }
    __syncthreads();
    if (tid < 16) {
        float s = 0.f, ss = 0.f;
        #pragma unroll
        for (int k = 0; k < 8; ++k) { s += s_red[0][tid][k]; ss += s_red[1][tid][k]; }
        atomicAdd(&stats[co0 + tid],        s);
        atomicAdd(&stats[COUT + co0 + tid], ss);
    }
}

// ================= conv2/conv3: implicit-GEMM tf32 mma.sync =================
// 256 threads = 8 warps. Tile: 64(W) x 16(H) px, 16 couts. Warp w: rows 2w,2w+1.
// CIN = 8*CHUNKS; K processed in CHUNKS chunks of (8 ci x 9 taps); m16n8k8 tf32.
// smem (words): s_w [CHUNKS*9*128) [chunk][tap][k8][m16]
//               s_in [.., +2*BSTR)  per ci: 18 rows x 72 words, CSTR=1304
//               s_red [.., +256)
#define CSTR 1304
#define BSTR (8*CSTR)
template<int CHUNKS, int COUT, bool WRITE_OUT, bool GATHER>
__global__ __launch_bounds__(256)
void conv_mma(const float* __restrict__ in,     // normalized tf32-rounded [B,CIN,H,W]
              const float* __restrict__ w,      // [COUT,CIN,3,3] fp32
              const float* __restrict__ bias,   // [COUT]
              float* __restrict__ out,
              float* __restrict__ stats,        // [sum COUT, sumsq COUT]
              float* __restrict__ gath,
              const int* __restrict__ nxy)
{
    constexpr int CIN = 8*CHUNKS;
    constexpr int WWORDS = CHUNKS*9*128;
    extern __shared__ float sm[];
    float* s_w   = sm;
    float* s_in  = sm + WWORDS;
    float* s_red = sm + WWORDS + 2*BSTR;    // [256]: sums then sumsqs

    const int tid  = threadIdx.x;
    const int lane = tid & 31;
    const int warp = tid >> 5;
    const int qr   = lane >> 2;     // m group / B n index
    const int qk   = lane & 3;      // k group / D col group
    const int tileX = blockIdx.x * 64, tileY = blockIdx.y * 16;
    constexpr int NG = COUT/16;
    const int b   = blockIdx.z / NG;
    const int co0 = (blockIdx.z % NG) * 16;

    // ---- preload + tf32-convert weights: [chunk][tap][k][m]
    for (int e = tid; e < WWORDS; e += 256) {
        int m   = e & 15;
        int k   = (e >> 4) & 7;
        int ct  = e >> 7;            // chunk*9 + tap
        int chunk = ct / 9;
        int tap   = ct - chunk*9;
        int ci    = chunk*8 + k;
        float wv = w[(co0 + m)*(CIN*9) + ci*9 + tap];
        s_w[e] = __uint_as_float(f2tf32(wv));
    }

    // ---- async halo copy for one 8-ci chunk: per ci 18 rows x 18 16B-granules
    auto copy_chunk = [&](int chunk, int buf) {
        const float* base = in + ((size_t)(b*CIN + chunk*8))*(HH*WW);
        #pragma unroll
        for (int it = 0; it < 11; ++it) {
            int e = tid + it*256;
            if (e < 2592) {
                int ci  = e / 324;
                int rem = e - ci*324;
                int r   = rem / 18;
                int g   = rem - r*18;
                int gy  = tileY + r - 1;
                int gxw = tileX - 4 + 4*g;
                bool ok = (gy >= 0) && (gy < HH) && (gxw >= 0) && (gxw + 3 < WW);
                const float* src = ok ? (base + ci*(HH*WW) + gy*WW + gxw) : base;
                uint32_t dst = (uint32_t)__cvta_generic_to_shared(
                    &s_in[buf*BSTR + ci*CSTR + r*72 + 4*g]);
                int sz = ok ? 16 : 0;
                asm volatile("cp.async.ca.shared.global [%0], [%1], 16, %2;"
                             :: "r"(dst), "l"(src), "r"(sz) : "memory");
            }
        }
    };

    float d[64];
    #pragma unroll
    for (int i = 0; i < 64; ++i) d[i] = 0.f;

    copy_chunk(0, 0);
    asm volatile("cp.async.commit_group;" ::: "memory");
    asm volatile("cp.async.wait_group 0;" ::: "memory");
    __syncthreads();

    for (int chunk = 0; chunk < CHUNKS; ++chunk) {
        const int buf = chunk & 1;
        const bool more = (chunk + 1 < CHUNKS);
        if (more) {
            copy_chunk(chunk + 1, buf ^ 1);
            asm volatile("cp.async.commit_group;" ::: "memory");
        }

        const float* sib = s_in + buf*BSTR;

        #pragma unroll
        for (int tap = 0; tap < 9; ++tap) {
            const int dy = tap / 3, dx = tap - 3*dy;
            const float* wq = s_w + ((chunk*9 + tap)*8 + qk)*16 + qr;
            uint32_t a0 = __float_as_uint(wq[0]);
            uint32_t a1 = __float_as_uint(wq[8]);
            uint32_t a2 = __float_as_uint(wq[64]);
            uint32_t a3 = __float_as_uint(wq[72]);

            #pragma unroll
            for (int jr = 0; jr < 2; ++jr) {
                const float* rowp = sib + (2*warp + jr + dy)*72 + 3 + dx + qr;
                #pragma unroll
                for (int jc = 0; jc < 8; ++jc) {
                    uint32_t b0 = __float_as_uint(rowp[qk*CSTR + 8*jc]);
                    uint32_t b1 = __float_as_uint(rowp[(qk + 4)*CSTR + 8*jc]);
                    float* dd = &d[4*(jr*8 + jc)];
                    asm("mma.sync.aligned.m16n8k8.row.col.f32.tf32.tf32.f32 "
                        "{%0,%1,%2,%3}, {%4,%5,%6,%7}, {%8,%9}, {%0,%1,%2,%3};"
                        : "+f"(dd[0]), "+f"(dd[1]), "+f"(dd[2]), "+f"(dd[3])
                        : "r"(a0), "r"(a1), "r"(a2), "r"(a3), "r"(b0), "r"(b1));
                }
            }
        }
        if (more) asm volatile("cp.async.wait_group 0;" ::: "memory");
        __syncthreads();
    }

    // ---- bias
    const float blo = bias[co0 + qr];
    const float bhi = bias[co0 + qr + 8];
    #pragma unroll
    for (int j = 0; j < 16; ++j) {
        d[4*j+0] += blo; d[4*j+1] += blo;
        d[4*j+2] += bhi; d[4*j+3] += bhi;
    }

    // ---- full fragment writeback (raw conv output)
    if (WRITE_OUT) {
        #pragma unroll
        for (int jr = 0; jr < 2; ++jr) {
            const int y = tileY + 2*warp + jr;
            #pragma unroll
            for (int jc = 0; jc < 8; ++jc) {
                const int x = tileX + 8*jc + 2*qk;
                const float* dd = &d[4*(jr*8 + jc)];
                *reinterpret_cast<float2*>(
                    &out[((size_t)(b*COUT + co0 + qr)*HH + y)*WW + x]) =
                    make_float2(dd[0], dd[1]);
                *reinterpret_cast<float2*>(
                    &out[((size_t)(b*COUT + co0 + qr + 8)*HH + y)*WW + x]) =
                    make_float2(dd[2], dd[3]);
            }
        }
    }

    // ---- gather (raw conv3 at target pixel)
    if (GATHER) {
        const int ny = nxy[b*64 + 62];
        const int nx = nxy[b*64 + 63];
        if (ny >= tileY && ny < tileY + 16 && nx >= tileX && nx < tileX + 64) {
            int lr = ny - tileY, lc = nx - tileX;
            if ((lr >> 1) == warp && qk == ((lc & 7) >> 1)) {
                int jt = (lr & 1)*8 + (lc >> 3);
                int sel = lc & 1;
                #pragma unroll
                for (int j = 0; j < 16; ++j) if (j == jt) {
                    gath[b*COUT + co0 + qr]     = d[4*j + sel];
                    gath[b*COUT + co0 + qr + 8] = d[4*j + 2 + sel];
                }
            }
        }
    }

    // ---- BN stats
    float slo = 0.f, sslo = 0.f, shi = 0.f, sshi = 0.f;
    #pragma unroll
    for (int j = 0; j < 16; ++j) {
        slo  += d[4*j+0] + d[4*j+1];
        sslo += d[4*j+0]*d[4*j+0] + d[4*j+1]*d[4*j+1];
        shi  += d[4*j+2] + d[4*j+3];
        sshi += d[4*j+2]*d[4*j+2] + d[4*j+3]*d[4*j+3];
    }
    slo  += __shfl_down_sync(0xffffffffu, slo,  2);
    slo  += __shfl_down_sync(0xffffffffu, slo,  1);
    sslo += __shfl_down_sync(0xffffffffu, sslo, 2);
    sslo += __shfl_down_sync(0xffffffffu, sslo, 1);
    shi  += __shfl_down_sync(0xffffffffu, shi,  2);
    shi  += __shfl_down_sync(0xffffffffu, shi,  1);
    sshi += __shfl_down_sync(0xffffffffu, sshi, 2);
    sshi += __shfl_down_sync(0xffffffffu, sshi, 1);
    if (qk == 0) {
        s_red[qr*8 + warp]             = slo;
        s_red[(qr + 8)*8 + warp]       = shi;
        s_red[128 + qr*8 + warp]       = sslo;
        s_red[128 + (qr + 8)*8 + warp] = sshi;
    }
    __syncthreads();
    if (tid < 16) {
        float s = 0.f, ss = 0.f;
        #pragma unroll
        for (int k = 0; k < 8; ++k) { s += s_red[tid*8 + k]; ss += s_red[128 + tid*8 + k]; }
        atomicAdd(&stats[co0 + tid],        s);
        atomicAdd(&stats[COUT + co0 + tid], ss);
    }
}

// ---------------- BN finalize ----------------
__global__ void finalize_aff(int C, int off,
                             const float* __restrict__ gamma,
                             const float* __restrict__ beta)
{
    int c = threadIdx.x;
    if (c < C) {
        const float n = (float)NPIX;
        float m = g_stats[off + c] / n;
        float v = g_stats[off + C + c] / n - m*m;
        float a = gamma[c] * rsqrtf(v + 1e-5f);
        g_aff[off + c]     = a;
        g_aff[off + C + c] = beta[c] - m*a;
    }
}

// ---------------- normalize + tf32 round ----------------
template<int C>
__global__ __launch_bounds__(256)
void normalize_tf32(float* __restrict__ y, const float* __restrict__ aff)
{
    int i = blockIdx.x*blockDim.x + threadIdx.x;
    int c = (i >> 14) & (C - 1);
    float sA = aff[c], sB = aff[C + c];
    float4 v = reinterpret_cast<float4*>(y)[i];
    v.x = fmaf(sA, v.x, sB); v.x = (v.x > 0.f) ? v.x : 0.01f*v.x;
    v.y = fmaf(sA, v.y, sB); v.y = (v.y > 0.f) ? v.y : 0.01f*v.y;
    v.z = fmaf(sA, v.z, sB); v.z = (v.z > 0.f) ? v.z : 0.01f*v.z;
    v.w = fmaf(sA, v.w, sB); v.w = (v.w > 0.f) ? v.w : 0.01f*v.w;
    v.x = __uint_as_float(f2tf32(v.x));
    v.y = __uint_as_float(f2tf32(v.y));
    v.z = __uint_as_float(f2tf32(v.z));
    v.w = __uint_as_float(f2tf32(v.w));
    reinterpret_cast<float4*>(y)[i] = v;
}

// ---------------- tail ----------------
__global__ void tail_kernel(const float* __restrict__ image,
                            const int* __restrict__ axy,
                            const int* __restrict__ pxy,
                            const int* __restrict__ nxy,
                            float* __restrict__ out)
{
    int i = blockIdx.x*blockDim.x + threadIdx.x;
    if (i < 3528) {
        int which = i / 1176;
        int rem   = i % 1176;
        int b  = rem / 147;
        int r2 = rem % 147;
        int c  = r2 / 49;
        int p  = r2 % 49;
        int pi = p / 7, pj = p % 7;
        const int* xy = (which == 0) ? axy : (which == 1) ? pxy : nxy;
        int y0 = xy[b*64 + 62] - 3;
        int x0 = xy[b*64 + 63] - 3;
        out[i] = image[((b*3 + c)*HH + (y0 + pi))*WW + (x0 + pj)];
    } else if (i < 3528 + 1024) {
        int j = i - 3528;
        int c = j & 127;
        float v = fmaf(g_aff[192 + c], g_gath[j], g_aff[192 + 128 + c]);
        out[i] = (v > 0.f) ? v : 0.01f*v;
    }
}

// ---------------- launch ----------------
extern "C" void kernel_launch(void* const* d_in, const int* in_sizes, int n_in,
                              void* d_out, int out_size)
{
    const float* image = (const float*)d_in[0];
    const int*   axy   = (const int*)  d_in[1];
    const int*   pxy   = (const int*)  d_in[2];
    const int*   nxy   = (const int*)  d_in[3];
    const float* w1 = (const float*)d_in[4];
    const float* b1 = (const float*)d_in[5];
    const float* g1 = (const float*)d_in[6];
    const float* e1 = (const float*)d_in[7];
    const float* w2 = (const float*)d_in[8];
    const float* b2 = (const float*)d_in[9];
    const float* g2 = (const float*)d_in[10];
    const float* e2 = (const float*)d_in[11];
    const float* w3 = (const float*)d_in[12];
    const float* b3 = (const float*)d_in[13];
    const float* g3 = (const float*)d_in[14];
    const float* e3 = (const float*)d_in[15];
    float* outp = (float*)d_out;

    float *y1, *y2, *stats, *aff, *gath;
    cudaGetSymbolAddress((void**)&y1,    g_y1);
    cudaGetSymbolAddress((void**)&y2,    g_y2);
    cudaGetSymbolAddress((void**)&stats, g_stats);
    cudaGetSymbolAddress((void**)&aff,   g_aff);
    cudaGetSymbolAddress((void**)&gath,  g_gath);

    const int SMEM2 = (4*9*128 + 2*BSTR + 256) * 4;   // conv2: 102912 B
    const int SMEM3 = (8*9*128 + 2*BSTR + 256) * 4;   // conv3: 121344 B
    cudaFuncSetAttribute((const void*)conv_mma<4, 64, true, false>,
                         cudaFuncAttributeMaxDynamicSharedMemorySize, SMEM2);
    cudaFuncSetAttribute((const void*)conv_mma<8, 128, false, true>,
                         cudaFuncAttributeMaxDynamicSharedMemorySize, SMEM3);

    dim3 blk(256);

    zero_stats<<<2, 256>>>();

    // conv1: image -> raw y1 + stats (fp32 FFMA2)
    conv3x3<3, 32><<<dim3(4,16,BB*2), blk>>>(image, w1, b1, y1, stats + 0);
    finalize_aff<<<1, 32>>>(32, 0, g1, e1);
    normalize_tf32<32><<<(BB*32*HH*WW/4)/256, 256>>>(y1, aff + 0);

    // conv2: tf32 mma implicit GEMM -> raw y2 + stats
    conv_mma<4, 64, true, false><<<dim3(4,16,BB*4), blk, SMEM2>>>(
        y1, w2, b2, y2, stats + 64, nullptr, nullptr);
    finalize_aff<<<1, 64>>>(64, 64, g2, e2);
    normalize_tf32<64><<<(BB*64*HH*WW/4)/256, 256>>>(y2, aff + 64);

    // conv3: tf32 mma implicit GEMM -> stats + gathered pixels (no store)
    conv_mma<8, 128, false, true><<<dim3(4,16,BB*8), blk, SMEM3>>>(
        y2, w3, b3, nullptr, stats + 192, gath, nxy);
    finalize_aff<<<1, 128>>>(128, 192, g3, e3);

    tail_kernel<<<(3528 + 1024 + 255)/256, 256>>>(image, axy, pxy, nxy, outp);
}